// round 14
// baseline (speedup 1.0000x reference)
#include <cuda_runtime.h>
#include <cuda_bf16.h>

// SurvLoss, single fused persistent kernel, 3 phases.
// log(cumsum(exp)) monotone => segment_max = value at LAST occurrence index.
// loss_s2 = sum_t ymax_t*cnt_t = sum_i E_i*ymax[seg_i]  => NO histogram:
// Phase A streams and writes packed (seg,E); Phase C gathers ymax.
//
// Phase A: stream 192MB; warp w of block b owns [b*16384+w*2048, +2048);
//          register exp-sum doubles as span sum (g_wsum). smem last-occ
//          filter+atomicMax only (count atomicAdd removed — it was ~half of
//          R12's runtime on the LSU). Writes packed u16 (seg<<1)|E (33MB).
// Barrier1: last arriver scans 1024 block sums (double, exclusive).
// Phase B: block b computes ymax[b] (span sums + <=2048-elem recompute).
// Barrier2: same pattern, second counter/flag.
// Phase C: block b reads its own packed slice, s2 += E*sy[seg] via
//          predicated LDS gather; finalize + reset all state.

#define NUM_TIMES 1024
#define NBLK      1024
#define THREADS   256
#define ITERS     16
#define TILE      16384

__device__ float              g_wsum[NBLK * 8];   // per-warp 2048-elem exp sums
__device__ float              g_block_agg[NBLK];
__device__ double             g_block_prefix[NBLK];
__device__ int                g_last[NUM_TIMES];  // 0 = empty, else idx+1
__device__ float              g_ymax[NUM_TIMES];
__device__ uint2              g_packed[NBLK * TILE / 4];   // 32MB
__device__ double             g_s1;
__device__ unsigned long long g_obs;
__device__ double             g_s2;
__device__ unsigned int       g_arrive1;
__device__ unsigned int       g_arrive2;
__device__ unsigned int       g_done;
__device__ __align__(128) volatile unsigned int g_release1[32];
__device__ __align__(128) volatile unsigned int g_release2[32];

__global__ void __launch_bounds__(THREADS, 8)
fused_main(const float* __restrict__ outs,
           const int* __restrict__ T_E,
           const int* __restrict__ T_T,
           float* __restrict__ out) {
    __shared__ int   s_last[NUM_TIMES];
    __shared__ float sy[NUM_TIMES];
    __shared__ float wtot[8];
    __shared__ float rs1[8];
    __shared__ int   rob[8];
    __shared__ int   s_flag;
    __shared__ int   sh_e;

    const int b = blockIdx.x, tid = threadIdx.x;
    const int lane = tid & 31, w = tid >> 5;

    for (int i = tid; i < NUM_TIMES; i += THREADS) s_last[i] = 0;
    __syncthreads();

    const float4* o4 = (const float4*)outs;
    const int4*   e4 = (const int4*)T_E;
    const int4*   t4 = (const int4*)T_T;
    // warp w owns contiguous float4s [b*4096 + w*512, +512)
    const int wbase = b * (TILE / 4) + w * 512;

    float thr_tot = 0.f;
    float ls1 = 0.f;
    int   lob = 0;

    // ---- Phase A: streaming (reverse order: filter kills most atomicMax) ----
#pragma unroll 8
    for (int c = ITERS - 1; c >= 0; --c) {
        const int fi = wbase + c * 32 + lane;
        float4 v  = o4[fi];
        int4   tt = t4[fi];
        int4   te = e4[fi];

        thr_tot += __expf(v.x) + __expf(v.y) + __expf(v.z) + __expf(v.w);

        const int gi = fi * 4;
        // T_T in [0, NUM_TIMES) by construction
        int sg0 = tt.x, sg1 = tt.y, sg2 = tt.z, sg3 = tt.w;

        if (s_last[sg3] < gi + 4) atomicMax(&s_last[sg3], gi + 4);
        if (s_last[sg2] < gi + 3) atomicMax(&s_last[sg2], gi + 3);
        if (s_last[sg1] < gi + 2) atomicMax(&s_last[sg1], gi + 2);
        if (s_last[sg0] < gi + 1) atomicMax(&s_last[sg0], gi + 1);

        // packed (seg<<1)|E — replaces the count histogram entirely
        uint2 pk;
        pk.x = (((unsigned)sg0 << 1) | (unsigned)(te.x != 0)) |
               ((((unsigned)sg1 << 1) | (unsigned)(te.y != 0)) << 16);
        pk.y = (((unsigned)sg2 << 1) | (unsigned)(te.z != 0)) |
               ((((unsigned)sg3 << 1) | (unsigned)(te.w != 0)) << 16);
        g_packed[fi] = pk;

        ls1 += te.x ? v.x : 0.f;
        ls1 += te.y ? v.y : 0.f;
        ls1 += te.z ? v.z : 0.f;
        ls1 += te.w ? v.w : 0.f;
        lob += (te.x != 0) + (te.y != 0) + (te.z != 0) + (te.w != 0);
    }

    // warp reduce: exp region sum (contiguous span), s1, obs
    float xx = thr_tot;
#pragma unroll
    for (int o = 16; o; o >>= 1) {
        xx  += __shfl_xor_sync(0xffffffffu, xx, o);
        ls1 += __shfl_xor_sync(0xffffffffu, ls1, o);
        lob += __shfl_xor_sync(0xffffffffu, lob, o);
    }
    if (lane == 0) {
        g_wsum[b * 8 + w] = xx;
        wtot[w] = xx; rs1[w] = ls1; rob[w] = lob;
    }
    __syncthreads();
    if (tid == 0) {
        float bt = 0.f, bs = 0.f; int bo = 0;
#pragma unroll
        for (int k = 0; k < 8; k++) { bt += wtot[k]; bs += rs1[k]; bo += rob[k]; }
        g_block_agg[b] = bt;
        atomicAdd(&g_s1, (double)bs);
        atomicAdd(&g_obs, (unsigned long long)bo);
    }

    // flush last-occurrence table
    __syncthreads();
    for (int i = tid; i < NUM_TIMES; i += THREADS) {
        int m = s_last[i];
        if (m) atomicMax(&g_last[i], m);
    }

    // ---- barrier 1 (all 1024 blocks resident: 8/SM * 148 = 1184) ----
    __threadfence();
    __syncthreads();
    if (tid == 0) s_flag = (atomicAdd(&g_arrive1, 1u) == NBLK - 1u);
    __syncthreads();
    if (s_flag) {
        // exclusive double scan of the 1024 block sums
        double v0 = (double)__ldcg(&g_block_agg[4 * tid + 0]);
        double v1 = (double)__ldcg(&g_block_agg[4 * tid + 1]);
        double v2 = (double)__ldcg(&g_block_agg[4 * tid + 2]);
        double v3 = (double)__ldcg(&g_block_agg[4 * tid + 3]);
        double c0 = v0, c1 = c0 + v1, c2 = c1 + v2, c3 = c2 + v3;

        double x = c3;
#pragma unroll
        for (int o = 1; o < 32; o <<= 1) {
            double y = __shfl_up_sync(0xffffffffu, x, o);
            if (lane >= o) x += y;
        }
        __shared__ double wsc[8];
        if (lane == 31) wsc[w] = x;
        __syncthreads();
        double wexcl = 0.0;
#pragma unroll
        for (int k = 0; k < 8; k++) if (k < w) wexcl += wsc[k];
        double excl = wexcl + (x - c3);

        g_block_prefix[4 * tid + 0] = excl;
        g_block_prefix[4 * tid + 1] = excl + c0;
        g_block_prefix[4 * tid + 2] = excl + c1;
        g_block_prefix[4 * tid + 3] = excl + c2;
        __syncthreads();
        if (tid == 0) { __threadfence(); atomicExch((unsigned int*)&g_release1[0], 1u); }
    } else {
        if (tid == 0) {
            int backoff = 32;
            while (g_release1[0] == 0u) { __nanosleep(backoff); if (backoff < 1024) backoff <<= 1; }
        }
        __syncthreads();
    }
    __threadfence();

    // ---- Phase B: block b computes ymax for segment b ----
    if (tid == 0) {
        sh_e = __ldcg(&g_last[b]);
        g_last[b] = 0;                        // sole reader -> reset
    }
    __syncthreads();
    const int e = sh_e;
    float ymv = 0.f;
    if (e > 0) {
        const int idx = e - 1;
        const int bo  = idx >> 14;            // owning tile
        const int wr  = (idx >> 11) & 7;      // warp-region in tile
        const int r   = idx & 2047;           // last included elem in region
        const int ql  = r >> 2;
        const int rem = r & 3;

        float acc = 0.f;
        if (tid < wr) acc = __ldcg(&g_wsum[bo * 8 + tid]);

        const float4* o4b = (const float4*)outs + bo * (TILE / 4) + wr * 512;
#pragma unroll
        for (int k = 0; k < 2; k++) {
            const int q = tid + k * THREADS;
            if (q <= ql) {
                float4 v = o4b[q];
                float s = __expf(v.x);
                if (q < ql) {
                    s += __expf(v.y) + __expf(v.z) + __expf(v.w);
                } else {
                    if (rem >= 1) s += __expf(v.y);
                    if (rem >= 2) s += __expf(v.z);
                    if (rem >= 3) s += __expf(v.w);
                }
                acc += s;
            }
        }
#pragma unroll
        for (int o = 16; o; o >>= 1) acc += __shfl_xor_sync(0xffffffffu, acc, o);
        if (lane == 0) wtot[w] = acc;
        __syncthreads();
        if (tid == 0) {
            float pt = 0.f;
#pragma unroll
            for (int kk = 0; kk < 8; kk++) pt += wtot[kk];
            double total = __ldcg(&g_block_prefix[bo]) + (double)pt;
            double y = log(total);
            ymv = (y < 0.0) ? 0.f : (float)y;
        }
    }
    if (tid == 0) g_ymax[b] = ymv;            // 0 if empty segment

    // ---- barrier 2 ----
    __threadfence();
    __syncthreads();
    if (tid == 0) s_flag = (atomicAdd(&g_arrive2, 1u) == NBLK - 1u);
    __syncthreads();
    if (s_flag) {
        if (tid == 0) { __threadfence(); atomicExch((unsigned int*)&g_release2[0], 1u); }
    } else {
        if (tid == 0) {
            int backoff = 32;
            while (g_release2[0] == 0u) { __nanosleep(backoff); if (backoff < 1024) backoff <<= 1; }
        }
        __syncthreads();
    }
    __threadfence();

    // ---- Phase C: gather s2 over own packed slice ----
    for (int i = tid; i < NUM_TIMES; i += THREADS) sy[i] = __ldcg(&g_ymax[i]);
    __syncthreads();

    float s2 = 0.f;
#pragma unroll 4
    for (int c = 0; c < ITERS; c++) {
        uint2 pk = g_packed[wbase + c * 32 + lane];
        unsigned a0 = pk.x & 0xffffu, a1 = pk.x >> 16;
        unsigned a2 = pk.y & 0xffffu, a3 = pk.y >> 16;
        if (a0 & 1) s2 += sy[a0 >> 1];
        if (a1 & 1) s2 += sy[a1 >> 1];
        if (a2 & 1) s2 += sy[a2 >> 1];
        if (a3 & 1) s2 += sy[a3 >> 1];
    }
    double d2 = (double)s2;
#pragma unroll
    for (int o = 16; o; o >>= 1) d2 += __shfl_xor_sync(0xffffffffu, d2, o);
    __shared__ double cs[8];
    if (lane == 0) cs[w] = d2;
    __syncthreads();
    if (tid == 0) {
        double s = 0.0;
#pragma unroll
        for (int k = 0; k < 8; k++) s += cs[k];
        atomicAdd(&g_s2, s);
    }

    // ---- finalize ----
    __threadfence();
    __syncthreads();
    if (tid == 0) {
        if (atomicAdd(&g_done, 1u) == NBLK - 1u) {
            double s2t = atomicAdd(&g_s2, 0.0);
            double s1t = atomicAdd(&g_s1, 0.0);
            unsigned long long obs = atomicAdd(&g_obs, 0ull);
            out[0] = (float)((s2t - s1t) / (double)obs);
            g_s2 = 0.0; g_s1 = 0.0; g_obs = 0ull;
            g_arrive1 = 0u; g_arrive2 = 0u; g_done = 0u;
            atomicExch((unsigned int*)&g_release1[0], 0u);
            atomicExch((unsigned int*)&g_release2[0], 0u);
        }
    }
}

// ---------------------------------------------------------------- launch
extern "C" void kernel_launch(void* const* d_in, const int* in_sizes, int n_in,
                              void* d_out, int out_size) {
    const float* outs = (const float*)d_in[0];
    const int*   T_E  = (const int*)d_in[1];
    const int*   T_T  = (const int*)d_in[2];
    float* out = (float*)d_out;

    fused_main<<<NBLK, THREADS>>>(outs, T_E, T_T, out);
}